// round 12
// baseline (speedup 1.0000x reference)
#include <cuda_runtime.h>
#include <cstdint>

// ---------------- problem constants (fixed by dataset) ----------------
#define NMAX 100000
#define EMAX 1250000
#define D    64
#define H    128
#define DV   (D / 4)   // 16 float4 per row
#define CAP  64        // fixed bin capacity (Poisson(12): overflow prob ~0)

// ---------------- device scratch (static allocation, allowed) ---------
// Replay invariants: g_cnt zeroed by k_gather; g_stats/g_ticket reset by
// k_fillbn finalize; g_srt live range bounded by g_cnt; g_agg4 rewritten.
__device__ int    g_cnt[ NMAX ];             // in-degree counts (bin cursor)
__device__ int    g_srt[ (size_t)NMAX * CAP ];  // fixed-capacity bins of src ids
__device__ float4 g_agg4[ (size_t)NMAX * DV ];  // normalized mean-aggregate
__device__ float  g_stats[ 2 * D ];          // colsum / colsumsq
__device__ float4 g_sc4[ DV ];               // BN scale per column (packed)
__device__ float4 g_sb4[ DV ];               // BN bias  per column (packed)
__device__ unsigned g_ticket;                // fillbn completion ticket

// ---------------- helpers ---------------------------------------------
__device__ __forceinline__ float f2tf32f(float x) {
    uint32_t r;
    asm("cvt.rna.tf32.f32 %0, %1;" : "=r"(r) : "f"(x));
    return __uint_as_float(r);
}

__device__ __forceinline__ void mma_tf32(float* c, const uint32_t* a,
                                         uint32_t b0, uint32_t b1) {
    asm("mma.sync.aligned.m16n8k8.row.col.f32.tf32.tf32.f32 "
        "{%0,%1,%2,%3}, {%4,%5,%6,%7}, {%8,%9}, {%0,%1,%2,%3};"
        : "+f"(c[0]), "+f"(c[1]), "+f"(c[2]), "+f"(c[3])
        : "r"(a[0]), "r"(a[1]), "r"(a[2]), "r"(a[3]), "r"(b0), "r"(b1));
}

// ---------------- kernel 1: edge fill + BN stats + finalize -----------
// Fill is atomic-latency-bound (issue ~6%), so the BN bandwidth pass
// rides along nearly free. Last-finished block computes sc/sb and
// resets g_stats/g_ticket (replay invariant).
__global__ void __launch_bounds__(256)
k_fillbn(const float4* __restrict__ x4, const int* __restrict__ ei,
         const float* __restrict__ gamma, const float* __restrict__ beta,
         int N, int E) {
    __shared__ float4 s_s4[16][16];
    __shared__ float4 s_q4[16][16];
    __shared__ bool   s_last;
    int t  = threadIdx.x;
    int c4 = t & 15, rg = t >> 4;

    // BN partial sums (thread-fixed column c4)
    float4 s = make_float4(0.f, 0.f, 0.f, 0.f);
    float4 q = make_float4(0.f, 0.f, 0.f, 0.f);
    for (int r = blockIdx.x * 16 + rg; r < N; r += gridDim.x * 16) {
        float4 v = x4[(size_t)r * DV + c4];
        s.x += v.x; s.y += v.y; s.z += v.z; s.w += v.w;
        q.x += v.x * v.x; q.y += v.y * v.y;
        q.z += v.z * v.z; q.w += v.w * v.w;
    }
    s_s4[rg][c4] = s; s_q4[rg][c4] = q;

    // edge fill into fixed-capacity bins
    for (int e = blockIdx.x * blockDim.x + t; e < E; e += gridDim.x * blockDim.x) {
        int dst = ei[(size_t)E + e];
        int src = ei[e];
        if ((unsigned)dst >= (unsigned)N || (unsigned)src >= (unsigned)N) continue;
        int pos = atomicAdd(&g_cnt[dst], 1);
        if (pos < CAP) g_srt[(size_t)dst * CAP + pos] = src;
    }

    __syncthreads();
    #pragma unroll
    for (int off = 8; off >= 1; off >>= 1) {
        if (rg < off) {
            float4 a = s_s4[rg + off][c4];
            float4 b = s_q4[rg + off][c4];
            s_s4[rg][c4].x += a.x; s_s4[rg][c4].y += a.y;
            s_s4[rg][c4].z += a.z; s_s4[rg][c4].w += a.w;
            s_q4[rg][c4].x += b.x; s_q4[rg][c4].y += b.y;
            s_q4[rg][c4].z += b.z; s_q4[rg][c4].w += b.w;
        }
        __syncthreads();
    }
    if (t < 16) {
        float4 S = s_s4[0][t], Q = s_q4[0][t];
        atomicAdd(&g_stats[t * 4 + 0], S.x); atomicAdd(&g_stats[t * 4 + 1], S.y);
        atomicAdd(&g_stats[t * 4 + 2], S.z); atomicAdd(&g_stats[t * 4 + 3], S.w);
        atomicAdd(&g_stats[D + t * 4 + 0], Q.x); atomicAdd(&g_stats[D + t * 4 + 1], Q.y);
        atomicAdd(&g_stats[D + t * 4 + 2], Q.z); atomicAdd(&g_stats[D + t * 4 + 3], Q.w);
    }
    __threadfence();
    if (t == 0)
        s_last = (atomicAdd(&g_ticket, 1u) == (unsigned)gridDim.x - 1u);
    __syncthreads();
    if (s_last && t < D) {
        float invN = 1.0f / (float)N;
        float mean = g_stats[t] * invN;
        float var  = g_stats[D + t] * invN - mean * mean;
        float inv  = rsqrtf(var + 1e-5f);
        float g    = gamma[t];
        reinterpret_cast<float*>(g_sc4)[t] = inv * g;
        reinterpret_cast<float*>(g_sb4)[t] = beta[t] - mean * inv * g;
        g_stats[t] = 0.f; g_stats[D + t] = 0.f;   // reset for next replay
        if (t == 0) g_ticket = 0u;
        __threadfence();
    }
}

// ---------------- kernel 2: high-occupancy bin gather -----------------
// Warp per node, lane owns float2 of the 64-dim row. Register accumulate,
// BN affine + mean applied once (cnt=0 -> exact 0). Zeroes g_cnt.
__global__ void __launch_bounds__(256)
k_gather(const float2* __restrict__ x2, int N) {
    int w    = threadIdx.x >> 5;
    int lane = threadIdx.x & 31;
    int node = blockIdx.x * 8 + w;
    if (node >= N) return;
    int cnt = min(g_cnt[node], CAP);
    if (lane == 0) g_cnt[node] = 0;            // replay invariant
    const int* bin = g_srt + (size_t)node * CAP;
    float sx = 0.f, sy = 0.f;
    int e = 0;
    for (; e + 4 <= cnt; e += 4) {
        int s0 = bin[e],     s1 = bin[e + 1];
        int s2 = bin[e + 2], s3 = bin[e + 3];
        float2 v0 = x2[(size_t)s0 * 32 + lane];
        float2 v1 = x2[(size_t)s1 * 32 + lane];
        float2 v2 = x2[(size_t)s2 * 32 + lane];
        float2 v3 = x2[(size_t)s3 * 32 + lane];
        sx += (v0.x + v1.x) + (v2.x + v3.x);
        sy += (v0.y + v1.y) + (v2.y + v3.y);
    }
    for (; e < cnt; e++) {
        int s0 = bin[e];
        float2 v0 = x2[(size_t)s0 * 32 + lane];
        sx += v0.x; sy += v0.y;
    }
    float2 o = make_float2(0.f, 0.f);
    if (cnt > 0) {
        float inv = 1.0f / (float)cnt;
        float scx = reinterpret_cast<const float*>(g_sc4)[2 * lane];
        float scy = reinterpret_cast<const float*>(g_sc4)[2 * lane + 1];
        float sbx = reinterpret_cast<const float*>(g_sb4)[2 * lane];
        float sby = reinterpret_cast<const float*>(g_sb4)[2 * lane + 1];
        o.x = fmaf(scx, sx * inv, sbx);
        o.y = fmaf(scy, sy * inv, sby);
    }
    reinterpret_cast<float2*>(g_agg4)[(size_t)node * 32 + lane] = o;
}

// ---------------- kernel 3: tf32 tensor-core GEMM + classifier --------
// h = relu([agg, xn] @ [W_l; W_r] + b_l)  (agg pre-normalized by gather)
// out = relu(h @ W1 + b1) @ W2 + b2, straight from mma fragments.
#define U_STRIDE 36
#define W_STRIDE 132
__global__ void __launch_bounds__(256)
k_fused_tc(const float4* __restrict__ x4,
           const float* __restrict__ Wl, const float* __restrict__ bl,
           const float* __restrict__ Wr, const float* __restrict__ W1,
           const float* __restrict__ b1, const float* __restrict__ W2,
           const float* __restrict__ b2, float* __restrict__ out, int N) {
    __shared__ float s_u [128 * U_STRIDE];   // U chunk  [128 rows][32 k], tf32
    __shared__ float s_w [32 * W_STRIDE];    // W chunk  [32 k][128 h], tf32
    __shared__ float s_w1t[16 * 128];        // W1^T [j][h]
    __shared__ float s_bl[128];
    __shared__ float s_scf[64], s_sbf[64];

    int t    = threadIdx.x;
    int w    = t >> 5;
    int lane = t & 31;
    int g    = lane >> 2;     // group id 0..7
    int tq   = lane & 3;      // thread-in-quad 0..3
    int m0   = blockIdx.x * 128;

    if (t < 128) s_bl[t] = bl[t];
    if (t < 64)  s_scf[t] = reinterpret_cast<const float*>(g_sc4)[t];
    else if (t < 128) s_sbf[t - 64] = reinterpret_cast<const float*>(g_sb4)[t - 64];
    for (int i = t; i < 16 * 128; i += 256) {      // W1 [128][16] -> W1T[j][h]
        int c = i & 127, j = i >> 7;
        s_w1t[j * 128 + c] = W1[c * 16 + j];
    }

    float acc[16][4];
    #pragma unroll
    for (int n = 0; n < 16; n++)
        #pragma unroll
        for (int j = 0; j < 4; j++) acc[n][j] = 0.f;

    #pragma unroll
    for (int kb = 0; kb < 4; kb++) {
        __syncthreads();
        // ---- load U chunk: 128 rows x 32 k (tf32) ----
        #pragma unroll
        for (int ii = 0; ii < 4; ii++) {
            int i = t + 256 * ii;            // 0..1023 float4 units
            int row = i >> 3, k4 = i & 7;
            int node = m0 + row;
            int kg = kb * 32 + k4 * 4;
            float4 v = make_float4(0.f, 0.f, 0.f, 0.f);
            if (node < N) {
                if (kg < D) {
                    v = g_agg4[(size_t)node * DV + (kg >> 2)];   // pre-normalized
                } else {
                    int kx = (kg - D) >> 2;
                    v = x4[(size_t)node * DV + kx];
                    int c = kx * 4;
                    v.x = fmaf(v.x, s_scf[c + 0], s_sbf[c + 0]);
                    v.y = fmaf(v.y, s_scf[c + 1], s_sbf[c + 1]);
                    v.z = fmaf(v.z, s_scf[c + 2], s_sbf[c + 2]);
                    v.w = fmaf(v.w, s_scf[c + 3], s_sbf[c + 3]);
                }
            }
            float* p = &s_u[row * U_STRIDE + k4 * 4];
            p[0] = f2tf32f(v.x); p[1] = f2tf32f(v.y);
            p[2] = f2tf32f(v.z); p[3] = f2tf32f(v.w);
        }
        // ---- load W chunk: 32 k x 128 h (tf32) ----
        #pragma unroll
        for (int ii = 0; ii < 4; ii++) {
            int i = t + 256 * ii;            // 0..1023 float4 units
            int k = i >> 5, h4 = i & 31;
            int kg = kb * 32 + k;
            const float* src = (kg < D) ? (Wl + (size_t)kg * H + h4 * 4)
                                        : (Wr + (size_t)(kg - D) * H + h4 * 4);
            float4 v = *reinterpret_cast<const float4*>(src);
            float* p = &s_w[k * W_STRIDE + h4 * 4];
            p[0] = f2tf32f(v.x); p[1] = f2tf32f(v.y);
            p[2] = f2tf32f(v.z); p[3] = f2tf32f(v.w);
        }
        __syncthreads();

        // ---- A fragments for this chunk (4 k-steps of 8) ----
        uint32_t A[4][4];
        int arow = (w * 16 + g) * U_STRIDE;
        #pragma unroll
        for (int kk = 0; kk < 4; kk++) {
            int kof = kk * 8 + tq;
            A[kk][0] = __float_as_uint(s_u[arow + kof]);
            A[kk][1] = __float_as_uint(s_u[arow + 8 * U_STRIDE + kof]);
            A[kk][2] = __float_as_uint(s_u[arow + kof + 4]);
            A[kk][3] = __float_as_uint(s_u[arow + 8 * U_STRIDE + kof + 4]);
        }
        // ---- 16 n-tiles x 4 k-steps of mma ----
        #pragma unroll
        for (int nt = 0; nt < 16; nt++) {
            int bcol = nt * 8 + g;
            #pragma unroll
            for (int kk = 0; kk < 4; kk++) {
                uint32_t b0  = __float_as_uint(s_w[(kk * 8 + tq) * W_STRIDE + bcol]);
                uint32_t b1r = __float_as_uint(s_w[(kk * 8 + tq + 4) * W_STRIDE + bcol]);
                mma_tf32(acc[nt], A[kk], b0, b1r);
            }
        }
    }

    // ---- epilogue: bias + relu + classifier, straight from fragments ----
    float part[2][16];
    #pragma unroll
    for (int rr = 0; rr < 2; rr++)
        #pragma unroll
        for (int j = 0; j < 16; j++) part[rr][j] = 0.f;

    #pragma unroll
    for (int nt = 0; nt < 16; nt++) {
        int c0 = nt * 8 + 2 * tq;
        float h00 = fmaxf(acc[nt][0] + s_bl[c0],     0.f);
        float h01 = fmaxf(acc[nt][1] + s_bl[c0 + 1], 0.f);
        float h10 = fmaxf(acc[nt][2] + s_bl[c0],     0.f);
        float h11 = fmaxf(acc[nt][3] + s_bl[c0 + 1], 0.f);
        #pragma unroll
        for (int j = 0; j < 16; j++) {
            float w0 = s_w1t[j * 128 + c0];
            float w1 = s_w1t[j * 128 + c0 + 1];
            part[0][j] += h00 * w0 + h01 * w1;
            part[1][j] += h10 * w0 + h11 * w1;
        }
    }
    #pragma unroll
    for (int rr = 0; rr < 2; rr++)
        #pragma unroll
        for (int j = 0; j < 16; j++) {
            part[rr][j] += __shfl_xor_sync(0xffffffffu, part[rr][j], 1);
            part[rr][j] += __shfl_xor_sync(0xffffffffu, part[rr][j], 2);
        }

    if (tq == 0) {
        #pragma unroll
        for (int rr = 0; rr < 2; rr++) {
            int node = m0 + w * 16 + g + rr * 8;
            if (node < N) {
                float o0 = b2[0], o1 = b2[1];
                #pragma unroll
                for (int j = 0; j < 16; j++) {
                    float tv = fmaxf(part[rr][j] + b1[j], 0.f);
                    o0 += tv * W2[j * 2 + 0];
                    o1 += tv * W2[j * 2 + 1];
                }
                out[(size_t)node * 2 + 0] = o0;
                out[(size_t)node * 2 + 1] = o1;
            }
        }
    }
}

// ---------------- launcher --------------------------------------------
extern "C" void kernel_launch(void* const* d_in, const int* in_sizes, int n_in,
                              void* d_out, int out_size) {
    const float4* x4 = (const float4*)d_in[0];
    const float2* x2 = (const float2*)d_in[0];
    const int*    ei = (const int*)d_in[1];   // int64 ref -> int32 in harness
    int N = in_sizes[0] / D;
    int E = in_sizes[1] / 2;

    const int want[9] = {64, 64, 8192, 128, 8192, 2048, 16, 32, 2};
    const float* wptr[9] = {nullptr, nullptr, nullptr, nullptr, nullptr,
                            nullptr, nullptr, nullptr, nullptr};
    int j = 0;
    for (int i = 2; i < n_in && j < 9; i++) {
        if (in_sizes[i] == want[j]) { wptr[j] = (const float*)d_in[i]; j++; }
    }
    const float *gamma = wptr[0], *beta = wptr[1], *Wl = wptr[2], *bl = wptr[3],
                *Wr = wptr[4], *W1 = wptr[5], *b1 = wptr[6], *W2 = wptr[7],
                *b2 = wptr[8];
    float* out = (float*)d_out;

    k_fillbn<<<2048, 256>>>(x4, ei, gamma, beta, N, E);
    k_gather<<<(N + 7) / 8, 256>>>(x2, N);
    k_fused_tc<<<(N + 127) / 128, 256>>>(x4, Wl, bl, Wr, W1, b1, W2, b2, out, N);
}

// round 14
// speedup vs baseline: 1.3274x; 1.3274x over previous
#include <cuda_runtime.h>
#include <cstdint>

// ---------------- problem constants (fixed by dataset) ----------------
#define NMAX 100000
#define EMAX 1250000
#define D    64
#define H    128
#define DV   (D / 4)   // 16 float4 per row

// ---------------- device scratch (static allocation, allowed) ---------
// Replay invariants: g_cnt + g_base zeroed by k_gather; g_stats/g_ticket
// reset by k_stats finalize; g_start/g_cur/g_srt/g_agg4 rewritten each replay.
__device__ int    g_cnt  [ NMAX ];    // in-degree counts
__device__ int    g_start[ NMAX ];    // CSR bin start per node
__device__ int    g_cur  [ NMAX ];    // fill cursor; after fill = bin end
__device__ int    g_srt  [ EMAX ];    // src ids grouped by dst
__device__ float4 g_agg4[ (size_t)NMAX * DV ];  // normalized mean-aggregate
__device__ float  g_stats[ 2 * D ];   // colsum / colsumsq
__device__ float4 g_sc4[ DV ];        // BN scale per column (packed)
__device__ float4 g_sb4[ DV ];        // BN bias  per column (packed)
__device__ unsigned g_ticket;         // k_stats completion ticket
__device__ int    g_base;             // global bin allocator

// ---------------- helpers ---------------------------------------------
__device__ __forceinline__ float f2tf32f(float x) {
    uint32_t r;
    asm("cvt.rna.tf32.f32 %0, %1;" : "=r"(r) : "f"(x));
    return __uint_as_float(r);
}

__device__ __forceinline__ void mma_tf32(float* c, const uint32_t* a,
                                         uint32_t b0, uint32_t b1) {
    asm("mma.sync.aligned.m16n8k8.row.col.f32.tf32.tf32.f32 "
        "{%0,%1,%2,%3}, {%4,%5,%6,%7}, {%8,%9}, {%0,%1,%2,%3};"
        : "+f"(c[0]), "+f"(c[1]), "+f"(c[2]), "+f"(c[3])
        : "r"(a[0]), "r"(a[1]), "r"(a[2]), "r"(a[3]), "r"(b0), "r"(b1));
}

// ---------------- kernel 1: BN stats + degree count + finalize --------
__global__ void k_stats(const float4* __restrict__ x4, const int* __restrict__ ei,
                        const float* __restrict__ gamma,
                        const float* __restrict__ beta, int N, int E) {
    __shared__ float4 s_s4[16][16];
    __shared__ float4 s_q4[16][16];
    __shared__ bool   s_last;
    int t  = threadIdx.x;
    int c4 = t & 15, rg = t >> 4;
    float4 s = make_float4(0.f, 0.f, 0.f, 0.f);
    float4 q = make_float4(0.f, 0.f, 0.f, 0.f);
    for (int r = blockIdx.x * 16 + rg; r < N; r += gridDim.x * 16) {
        float4 v = x4[(size_t)r * DV + c4];
        s.x += v.x; s.y += v.y; s.z += v.z; s.w += v.w;
        q.x += v.x * v.x; q.y += v.y * v.y;
        q.z += v.z * v.z; q.w += v.w * v.w;
    }
    s_s4[rg][c4] = s; s_q4[rg][c4] = q;

    // fused in-degree counting (independent work, spread reductions)
    for (int e = blockIdx.x * blockDim.x + t; e < E; e += gridDim.x * blockDim.x) {
        int dst = ei[(size_t)E + e];
        int src = ei[e];
        if ((unsigned)dst < (unsigned)N && (unsigned)src < (unsigned)N)
            atomicAdd(&g_cnt[dst], 1);
    }
    __syncthreads();
    #pragma unroll
    for (int off = 8; off >= 1; off >>= 1) {
        if (rg < off) {
            float4 a = s_s4[rg + off][c4];
            float4 b = s_q4[rg + off][c4];
            s_s4[rg][c4].x += a.x; s_s4[rg][c4].y += a.y;
            s_s4[rg][c4].z += a.z; s_s4[rg][c4].w += a.w;
            s_q4[rg][c4].x += b.x; s_q4[rg][c4].y += b.y;
            s_q4[rg][c4].z += b.z; s_q4[rg][c4].w += b.w;
        }
        __syncthreads();
    }
    if (t < 16) {
        float4 S = s_s4[0][t], Q = s_q4[0][t];
        atomicAdd(&g_stats[t * 4 + 0], S.x); atomicAdd(&g_stats[t * 4 + 1], S.y);
        atomicAdd(&g_stats[t * 4 + 2], S.z); atomicAdd(&g_stats[t * 4 + 3], S.w);
        atomicAdd(&g_stats[D + t * 4 + 0], Q.x); atomicAdd(&g_stats[D + t * 4 + 1], Q.y);
        atomicAdd(&g_stats[D + t * 4 + 2], Q.z); atomicAdd(&g_stats[D + t * 4 + 3], Q.w);
    }
    __threadfence();
    if (t == 0)
        s_last = (atomicAdd(&g_ticket, 1u) == (unsigned)gridDim.x - 1u);
    __syncthreads();
    if (s_last && t < D) {
        float invN = 1.0f / (float)N;
        float mean = g_stats[t] * invN;
        float var  = g_stats[D + t] * invN - mean * mean;
        float inv  = rsqrtf(var + 1e-5f);
        float g    = gamma[t];
        reinterpret_cast<float*>(g_sc4)[t] = inv * g;
        reinterpret_cast<float*>(g_sb4)[t] = beta[t] - mean * inv * g;
        g_stats[t] = 0.f; g_stats[D + t] = 0.f;   // reset for next replay
        if (t == 0) g_ticket = 0u;
        __threadfence();
    }
}

// ---------------- kernel 2: parallel bin offsets ----------------------
__global__ void __launch_bounds__(1024)
k_offsets(int N) {
    __shared__ int s[1024];
    __shared__ int s_base;
    int t = threadIdx.x;
    int i = blockIdx.x * 1024 + t;
    int c = (i < N) ? g_cnt[i] : 0;
    s[t] = c;
    __syncthreads();
    for (int off = 1; off < 1024; off <<= 1) {
        int v = (t >= off) ? s[t - off] : 0;
        __syncthreads();
        s[t] += v;
        __syncthreads();
    }
    if (t == 1023) s_base = atomicAdd(&g_base, s[1023]);
    __syncthreads();
    if (i < N) {
        int st = s_base + s[t] - c;
        g_start[i] = st;
        g_cur[i]   = st;
    }
}

// ---------------- kernel 3: CSR fill (bin src ids by dst) -------------
__global__ void k_fill(const int* __restrict__ ei, int E, int N) {
    int i = blockIdx.x * blockDim.x + threadIdx.x;
    int stride = gridDim.x * blockDim.x;
    for (int e = i; e < E; e += stride) {
        int dst = ei[(size_t)E + e];
        int src = ei[e];
        if ((unsigned)dst >= (unsigned)N || (unsigned)src >= (unsigned)N) continue;
        int pos = atomicAdd(&g_cur[dst], 1);
        g_srt[pos] = src;
    }
}

// ---------------- kernel 4: high-occupancy CSR gather -----------------
__global__ void __launch_bounds__(256)
k_gather(const float2* __restrict__ x2, int N) {
    int w    = threadIdx.x >> 5;
    int lane = threadIdx.x & 31;
    int node = blockIdx.x * 8 + w;
    if (threadIdx.x == 0 && blockIdx.x == 0) g_base = 0;   // replay invariant
    if (node >= N) return;
    if (lane == 0) g_cnt[node] = 0;                        // replay invariant
    int start = g_start[node];
    int end   = g_cur[node];
    float sx = 0.f, sy = 0.f;
    int e = start;
    for (; e + 4 <= end; e += 4) {
        int s0 = g_srt[e],     s1 = g_srt[e + 1];
        int s2 = g_srt[e + 2], s3 = g_srt[e + 3];
        float2 v0 = x2[(size_t)s0 * 32 + lane];
        float2 v1 = x2[(size_t)s1 * 32 + lane];
        float2 v2 = x2[(size_t)s2 * 32 + lane];
        float2 v3 = x2[(size_t)s3 * 32 + lane];
        sx += (v0.x + v1.x) + (v2.x + v3.x);
        sy += (v0.y + v1.y) + (v2.y + v3.y);
    }
    for (; e < end; e++) {
        int s0 = g_srt[e];
        float2 v0 = x2[(size_t)s0 * 32 + lane];
        sx += v0.x; sy += v0.y;
    }
    int cnt = end - start;
    float2 o = make_float2(0.f, 0.f);
    if (cnt > 0) {
        float inv = 1.0f / (float)cnt;
        float scx = reinterpret_cast<const float*>(g_sc4)[2 * lane];
        float scy = reinterpret_cast<const float*>(g_sc4)[2 * lane + 1];
        float sbx = reinterpret_cast<const float*>(g_sb4)[2 * lane];
        float sby = reinterpret_cast<const float*>(g_sb4)[2 * lane + 1];
        o.x = fmaf(scx, sx * inv, sbx);
        o.y = fmaf(scy, sy * inv, sby);
    }
    reinterpret_cast<float2*>(g_agg4)[(size_t)node * 32 + lane] = o;
}

// ---------------- kernel 5: tf32 GEMM + mma classifier ----------------
// h = relu([agg, xn] @ [W_l; W_r] + b_l)      (tf32 mma, fp32 accum)
// t = relu(h @ W1 + b1)  via mma too (h restaged through s_u, 32 cols/pass)
// out = t @ W2 + b2      from fragments + quad butterfly.
#define U_STRIDE   36
#define W_STRIDE   132
#define W1T_STRIDE 132
__global__ void __launch_bounds__(256)
k_fused_tc(const float4* __restrict__ x4,
           const float* __restrict__ Wl, const float* __restrict__ bl,
           const float* __restrict__ Wr, const float* __restrict__ W1,
           const float* __restrict__ b1, const float* __restrict__ W2,
           const float* __restrict__ b2, float* __restrict__ out, int N) {
    __shared__ float s_u [128 * U_STRIDE];   // U chunk [128 rows][32 k], tf32 (reused for h)
    __shared__ float s_w [32 * W_STRIDE];    // W chunk [32 k][128 h], tf32
    __shared__ float s_w1t[16 * W1T_STRIDE]; // W1^T [n=16][k=128], tf32
    __shared__ float s_bl[128];
    __shared__ float s_scf[64], s_sbf[64];

    int t    = threadIdx.x;
    int w    = t >> 5;
    int lane = t & 31;
    int g    = lane >> 2;     // group id 0..7
    int tq   = lane & 3;      // thread-in-quad 0..3
    int m0   = blockIdx.x * 128;

    if (t < 128) s_bl[t] = bl[t];
    if (t < 64)  s_scf[t] = reinterpret_cast<const float*>(g_sc4)[t];
    else if (t < 128) s_sbf[t - 64] = reinterpret_cast<const float*>(g_sb4)[t - 64];
    for (int i = t; i < 16 * 128; i += 256) {   // W1 [128][16] -> W1T[n][k], tf32
        int c = i & 127, j = i >> 7;
        s_w1t[j * W1T_STRIDE + c] = f2tf32f(W1[c * 16 + j]);
    }

    float acc[16][4];
    #pragma unroll
    for (int n = 0; n < 16; n++)
        #pragma unroll
        for (int j = 0; j < 4; j++) acc[n][j] = 0.f;

    #pragma unroll
    for (int kb = 0; kb < 4; kb++) {
        __syncthreads();
        // ---- load U chunk: 128 rows x 32 k (tf32) ----
        #pragma unroll
        for (int ii = 0; ii < 4; ii++) {
            int i = t + 256 * ii;            // 0..1023 float4 units
            int row = i >> 3, k4 = i & 7;
            int node = m0 + row;
            int kg = kb * 32 + k4 * 4;
            float4 v = make_float4(0.f, 0.f, 0.f, 0.f);
            if (node < N) {
                if (kg < D) {
                    v = g_agg4[(size_t)node * DV + (kg >> 2)];   // pre-normalized
                } else {
                    int kx = (kg - D) >> 2;
                    v = x4[(size_t)node * DV + kx];
                    int c = kx * 4;
                    v.x = fmaf(v.x, s_scf[c + 0], s_sbf[c + 0]);
                    v.y = fmaf(v.y, s_scf[c + 1], s_sbf[c + 1]);
                    v.z = fmaf(v.z, s_scf[c + 2], s_sbf[c + 2]);
                    v.w = fmaf(v.w, s_scf[c + 3], s_sbf[c + 3]);
                }
            }
            float* p = &s_u[row * U_STRIDE + k4 * 4];
            p[0] = f2tf32f(v.x); p[1] = f2tf32f(v.y);
            p[2] = f2tf32f(v.z); p[3] = f2tf32f(v.w);
        }
        // ---- load W chunk: 32 k x 128 h (tf32) ----
        #pragma unroll
        for (int ii = 0; ii < 4; ii++) {
            int i = t + 256 * ii;            // 0..1023 float4 units
            int k = i >> 5, h4 = i & 31;
            int kg = kb * 32 + k;
            const float* src = (kg < D) ? (Wl + (size_t)kg * H + h4 * 4)
                                        : (Wr + (size_t)(kg - D) * H + h4 * 4);
            float4 v = *reinterpret_cast<const float4*>(src);
            float* p = &s_w[k * W_STRIDE + h4 * 4];
            p[0] = f2tf32f(v.x); p[1] = f2tf32f(v.y);
            p[2] = f2tf32f(v.z); p[3] = f2tf32f(v.w);
        }
        __syncthreads();

        // ---- A fragments for this chunk (4 k-steps of 8) ----
        uint32_t A[4][4];
        int arow = (w * 16 + g) * U_STRIDE;
        #pragma unroll
        for (int kk = 0; kk < 4; kk++) {
            int kof = kk * 8 + tq;
            A[kk][0] = __float_as_uint(s_u[arow + kof]);
            A[kk][1] = __float_as_uint(s_u[arow + 8 * U_STRIDE + kof]);
            A[kk][2] = __float_as_uint(s_u[arow + kof + 4]);
            A[kk][3] = __float_as_uint(s_u[arow + 8 * U_STRIDE + kof + 4]);
        }
        // ---- 16 n-tiles x 4 k-steps of mma ----
        #pragma unroll
        for (int nt = 0; nt < 16; nt++) {
            int bcol = nt * 8 + g;
            #pragma unroll
            for (int kk = 0; kk < 4; kk++) {
                uint32_t b0  = __float_as_uint(s_w[(kk * 8 + tq) * W_STRIDE + bcol]);
                uint32_t b1r = __float_as_uint(s_w[(kk * 8 + tq + 4) * W_STRIDE + bcol]);
                mma_tf32(acc[nt], A[kk], b0, b1r);
            }
        }
    }

    // ---- classifier GEMM: t = relu(h@W1+b1) via mma, 32 h-cols/pass ----
    float acc2[2][4];
    #pragma unroll
    for (int n = 0; n < 2; n++)
        #pragma unroll
        for (int j = 0; j < 4; j++) acc2[n][j] = 0.f;

    #pragma unroll
    for (int cb = 0; cb < 4; cb++) {
        __syncthreads();   // prior pass (or mainloop) done with s_u
        // stage relu(h + bl) for h-cols [cb*32, cb*32+32) into s_u
        #pragma unroll
        for (int ntl = 0; ntl < 4; ntl++) {
            int nt = cb * 4 + ntl;
            int c0g = nt * 8 + 2 * tq;          // global h col
            int cl  = ntl * 8 + 2 * tq;         // local col in chunk
            int r0 = (w * 16 + g) * U_STRIDE;
            int r1 = r0 + 8 * U_STRIDE;
            s_u[r0 + cl]     = f2tf32f(fmaxf(acc[nt][0] + s_bl[c0g],     0.f));
            s_u[r0 + cl + 1] = f2tf32f(fmaxf(acc[nt][1] + s_bl[c0g + 1], 0.f));
            s_u[r1 + cl]     = f2tf32f(fmaxf(acc[nt][2] + s_bl[c0g],     0.f));
            s_u[r1 + cl + 1] = f2tf32f(fmaxf(acc[nt][3] + s_bl[c0g + 1], 0.f));
        }
        __syncthreads();
        int arow = (w * 16 + g) * U_STRIDE;
        #pragma unroll
        for (int kk = 0; kk < 4; kk++) {
            int kof = kk * 8 + tq;
            uint32_t Af[4];
            Af[0] = __float_as_uint(s_u[arow + kof]);
            Af[1] = __float_as_uint(s_u[arow + 8 * U_STRIDE + kof]);
            Af[2] = __float_as_uint(s_u[arow + kof + 4]);
            Af[3] = __float_as_uint(s_u[arow + 8 * U_STRIDE + kof + 4]);
            #pragma unroll
            for (int nt2 = 0; nt2 < 2; nt2++) {
                int kg = cb * 32 + kk * 8 + tq;
                uint32_t b0  = __float_as_uint(s_w1t[(nt2 * 8 + g) * W1T_STRIDE + kg]);
                uint32_t b1r = __float_as_uint(s_w1t[(nt2 * 8 + g) * W1T_STRIDE + kg + 4]);
                mma_tf32(acc2[nt2], Af, b0, b1r);
            }
        }
    }

    // ---- final 16 -> 2 projection from fragments ----
    float o0[2] = {0.f, 0.f}, o1[2] = {0.f, 0.f};
    #pragma unroll
    for (int nt2 = 0; nt2 < 2; nt2++) {
        int j0 = nt2 * 8 + 2 * tq;
        float t00 = fmaxf(acc2[nt2][0] + b1[j0],     0.f);
        float t01 = fmaxf(acc2[nt2][1] + b1[j0 + 1], 0.f);
        float t10 = fmaxf(acc2[nt2][2] + b1[j0],     0.f);
        float t11 = fmaxf(acc2[nt2][3] + b1[j0 + 1], 0.f);
        float w00 = W2[j0 * 2],       w01 = W2[j0 * 2 + 1];
        float w10 = W2[(j0 + 1) * 2], w11 = W2[(j0 + 1) * 2 + 1];
        o0[0] += t00 * w00 + t01 * w10;  o1[0] += t00 * w01 + t01 * w11;
        o0[1] += t10 * w00 + t11 * w10;  o1[1] += t10 * w01 + t11 * w11;
    }
    #pragma unroll
    for (int rr = 0; rr < 2; rr++) {
        o0[rr] += __shfl_xor_sync(0xffffffffu, o0[rr], 1);
        o0[rr] += __shfl_xor_sync(0xffffffffu, o0[rr], 2);
        o1[rr] += __shfl_xor_sync(0xffffffffu, o1[rr], 1);
        o1[rr] += __shfl_xor_sync(0xffffffffu, o1[rr], 2);
    }
    if (tq == 0) {
        #pragma unroll
        for (int rr = 0; rr < 2; rr++) {
            int node = m0 + w * 16 + g + rr * 8;
            if (node < N) {
                out[(size_t)node * 2 + 0] = o0[rr] + b2[0];
                out[(size_t)node * 2 + 1] = o1[rr] + b2[1];
            }
        }
    }
}

// ---------------- launcher --------------------------------------------
extern "C" void kernel_launch(void* const* d_in, const int* in_sizes, int n_in,
                              void* d_out, int out_size) {
    const float4* x4 = (const float4*)d_in[0];
    const float2* x2 = (const float2*)d_in[0];
    const int*    ei = (const int*)d_in[1];   // int64 ref -> int32 in harness
    int N = in_sizes[0] / D;
    int E = in_sizes[1] / 2;

    const int want[9] = {64, 64, 8192, 128, 8192, 2048, 16, 32, 2};
    const float* wptr[9] = {nullptr, nullptr, nullptr, nullptr, nullptr,
                            nullptr, nullptr, nullptr, nullptr};
    int j = 0;
    for (int i = 2; i < n_in && j < 9; i++) {
        if (in_sizes[i] == want[j]) { wptr[j] = (const float*)d_in[i]; j++; }
    }
    const float *gamma = wptr[0], *beta = wptr[1], *Wl = wptr[2], *bl = wptr[3],
                *Wr = wptr[4], *W1 = wptr[5], *b1 = wptr[6], *W2 = wptr[7],
                *b2 = wptr[8];
    float* out = (float*)d_out;

    k_stats<<<592, 256>>>(x4, ei, gamma, beta, N, E);
    k_offsets<<<(N + 1023) / 1024, 1024>>>(N);
    k_fill<<<2048, 256>>>(ei, E, N);
    k_gather<<<(N + 7) / 8, 256>>>(x2, N);
    k_fused_tc<<<(N + 127) / 128, 256>>>(x4, Wl, bl, Wr, W1, b1, W2, b2, out, N);
}

// round 15
// speedup vs baseline: 1.7780x; 1.3394x over previous
#include <cuda_runtime.h>
#include <cstdint>

// ---------------- problem constants (fixed by dataset) ----------------
#define NMAX 100000
#define EMAX 1250000
#define D    64
#define H    128
#define DV   (D / 4)   // 16 float4 per row

// ---------------- device scratch (static allocation, allowed) ---------
// Replay invariants: g_cnt + g_base zeroed by k_gather; g_stats/g_ticket
// reset by k_stats finalize; g_start/g_cur/g_srt/g_agg4 rewritten each replay.
__device__ int    g_cnt  [ NMAX ];    // in-degree counts
__device__ int    g_start[ NMAX ];    // CSR bin start per node
__device__ int    g_cur  [ NMAX ];    // fill cursor; after fill = bin end
__device__ int    g_srt  [ EMAX ];    // src ids grouped by dst
__device__ float4 g_agg4[ (size_t)NMAX * DV ];  // normalized mean-aggregate
__device__ float  g_stats[ 2 * D ];   // colsum / colsumsq
__device__ float4 g_sc4[ DV ];        // BN scale per column (packed)
__device__ float4 g_sb4[ DV ];        // BN bias  per column (packed)
__device__ unsigned g_ticket;         // k_stats completion ticket
__device__ int    g_base;             // global bin allocator

// ---------------- helpers ---------------------------------------------
__device__ __forceinline__ float f2tf32f(float x) {
    uint32_t r;
    asm("cvt.rna.tf32.f32 %0, %1;" : "=r"(r) : "f"(x));
    return __uint_as_float(r);
}

__device__ __forceinline__ void mma_tf32(float* c, const uint32_t* a,
                                         uint32_t b0, uint32_t b1) {
    asm("mma.sync.aligned.m16n8k8.row.col.f32.tf32.tf32.f32 "
        "{%0,%1,%2,%3}, {%4,%5,%6,%7}, {%8,%9}, {%0,%1,%2,%3};"
        : "+f"(c[0]), "+f"(c[1]), "+f"(c[2]), "+f"(c[3])
        : "r"(a[0]), "r"(a[1]), "r"(a[2]), "r"(a[3]), "r"(b0), "r"(b1));
}

// ---------------- kernel 1: BN stats + degree count + finalize --------
__global__ void k_stats(const float4* __restrict__ x4, const int* __restrict__ ei,
                        const float* __restrict__ gamma,
                        const float* __restrict__ beta, int N, int E) {
    __shared__ float4 s_s4[16][16];
    __shared__ float4 s_q4[16][16];
    __shared__ bool   s_last;
    int t  = threadIdx.x;
    int c4 = t & 15, rg = t >> 4;
    float4 s = make_float4(0.f, 0.f, 0.f, 0.f);
    float4 q = make_float4(0.f, 0.f, 0.f, 0.f);
    for (int r = blockIdx.x * 16 + rg; r < N; r += gridDim.x * 16) {
        float4 v = x4[(size_t)r * DV + c4];
        s.x += v.x; s.y += v.y; s.z += v.z; s.w += v.w;
        q.x += v.x * v.x; q.y += v.y * v.y;
        q.z += v.z * v.z; q.w += v.w * v.w;
    }
    s_s4[rg][c4] = s; s_q4[rg][c4] = q;

    // fused in-degree counting (independent work, spread reductions)
    for (int e = blockIdx.x * blockDim.x + t; e < E; e += gridDim.x * blockDim.x) {
        int dst = ei[(size_t)E + e];
        int src = ei[e];
        if ((unsigned)dst < (unsigned)N && (unsigned)src < (unsigned)N)
            atomicAdd(&g_cnt[dst], 1);
    }
    __syncthreads();
    #pragma unroll
    for (int off = 8; off >= 1; off >>= 1) {
        if (rg < off) {
            float4 a = s_s4[rg + off][c4];
            float4 b = s_q4[rg + off][c4];
            s_s4[rg][c4].x += a.x; s_s4[rg][c4].y += a.y;
            s_s4[rg][c4].z += a.z; s_s4[rg][c4].w += a.w;
            s_q4[rg][c4].x += b.x; s_q4[rg][c4].y += b.y;
            s_q4[rg][c4].z += b.z; s_q4[rg][c4].w += b.w;
        }
        __syncthreads();
    }
    if (t < 16) {
        float4 S = s_s4[0][t], Q = s_q4[0][t];
        atomicAdd(&g_stats[t * 4 + 0], S.x); atomicAdd(&g_stats[t * 4 + 1], S.y);
        atomicAdd(&g_stats[t * 4 + 2], S.z); atomicAdd(&g_stats[t * 4 + 3], S.w);
        atomicAdd(&g_stats[D + t * 4 + 0], Q.x); atomicAdd(&g_stats[D + t * 4 + 1], Q.y);
        atomicAdd(&g_stats[D + t * 4 + 2], Q.z); atomicAdd(&g_stats[D + t * 4 + 3], Q.w);
    }
    __threadfence();
    if (t == 0)
        s_last = (atomicAdd(&g_ticket, 1u) == (unsigned)gridDim.x - 1u);
    __syncthreads();
    if (s_last && t < D) {
        float invN = 1.0f / (float)N;
        float mean = g_stats[t] * invN;
        float var  = g_stats[D + t] * invN - mean * mean;
        float inv  = rsqrtf(var + 1e-5f);
        float g    = gamma[t];
        reinterpret_cast<float*>(g_sc4)[t] = inv * g;
        reinterpret_cast<float*>(g_sb4)[t] = beta[t] - mean * inv * g;
        g_stats[t] = 0.f; g_stats[D + t] = 0.f;   // reset for next replay
        if (t == 0) g_ticket = 0u;
        __threadfence();
    }
}

// ---------------- kernel 2: parallel bin offsets ----------------------
__global__ void __launch_bounds__(1024)
k_offsets(int N) {
    __shared__ int s[1024];
    __shared__ int s_base;
    int t = threadIdx.x;
    int i = blockIdx.x * 1024 + t;
    int c = (i < N) ? g_cnt[i] : 0;
    s[t] = c;
    __syncthreads();
    for (int off = 1; off < 1024; off <<= 1) {
        int v = (t >= off) ? s[t - off] : 0;
        __syncthreads();
        s[t] += v;
        __syncthreads();
    }
    if (t == 1023) s_base = atomicAdd(&g_base, s[1023]);
    __syncthreads();
    if (i < N) {
        int st = s_base + s[t] - c;
        g_start[i] = st;
        g_cur[i]   = st;
    }
}

// ---------------- kernel 3: CSR fill, 2-way independent atomic ILP ----
__global__ void k_fill(const int* __restrict__ ei, int E, int N) {
    int i = blockIdx.x * blockDim.x + threadIdx.x;
    int stride = gridDim.x * blockDim.x;
    int e = i;
    for (; e + stride < E; e += 2 * stride) {
        int e1 = e + stride;
        int dst0 = ei[(size_t)E + e],  src0 = ei[e];
        int dst1 = ei[(size_t)E + e1], src1 = ei[e1];
        bool ok0 = (unsigned)dst0 < (unsigned)N && (unsigned)src0 < (unsigned)N;
        bool ok1 = (unsigned)dst1 < (unsigned)N && (unsigned)src1 < (unsigned)N;
        int pos0 = ok0 ? atomicAdd(&g_cur[dst0], 1) : 0;
        int pos1 = ok1 ? atomicAdd(&g_cur[dst1], 1) : 0;
        if (ok0) g_srt[pos0] = src0;
        if (ok1) g_srt[pos1] = src1;
    }
    for (; e < E; e += stride) {
        int dst = ei[(size_t)E + e];
        int src = ei[e];
        if ((unsigned)dst >= (unsigned)N || (unsigned)src >= (unsigned)N) continue;
        int pos = atomicAdd(&g_cur[dst], 1);
        g_srt[pos] = src;
    }
}

// ---------------- kernel 4: high-occupancy CSR gather -----------------
__global__ void __launch_bounds__(256)
k_gather(const float2* __restrict__ x2, int N) {
    int w    = threadIdx.x >> 5;
    int lane = threadIdx.x & 31;
    int node = blockIdx.x * 8 + w;
    if (threadIdx.x == 0 && blockIdx.x == 0) g_base = 0;   // replay invariant
    if (node >= N) return;
    if (lane == 0) g_cnt[node] = 0;                        // replay invariant
    int start = g_start[node];
    int end   = g_cur[node];
    float sx = 0.f, sy = 0.f;
    int e = start;
    for (; e + 4 <= end; e += 4) {
        int s0 = g_srt[e],     s1 = g_srt[e + 1];
        int s2 = g_srt[e + 2], s3 = g_srt[e + 3];
        float2 v0 = x2[(size_t)s0 * 32 + lane];
        float2 v1 = x2[(size_t)s1 * 32 + lane];
        float2 v2 = x2[(size_t)s2 * 32 + lane];
        float2 v3 = x2[(size_t)s3 * 32 + lane];
        sx += (v0.x + v1.x) + (v2.x + v3.x);
        sy += (v0.y + v1.y) + (v2.y + v3.y);
    }
    for (; e < end; e++) {
        int s0 = g_srt[e];
        float2 v0 = x2[(size_t)s0 * 32 + lane];
        sx += v0.x; sy += v0.y;
    }
    int cnt = end - start;
    float2 o = make_float2(0.f, 0.f);
    if (cnt > 0) {
        float inv = 1.0f / (float)cnt;
        float scx = reinterpret_cast<const float*>(g_sc4)[2 * lane];
        float scy = reinterpret_cast<const float*>(g_sc4)[2 * lane + 1];
        float sbx = reinterpret_cast<const float*>(g_sb4)[2 * lane];
        float sby = reinterpret_cast<const float*>(g_sb4)[2 * lane + 1];
        o.x = fmaf(scx, sx * inv, sbx);
        o.y = fmaf(scy, sy * inv, sby);
    }
    reinterpret_cast<float2*>(g_agg4)[(size_t)node * 32 + lane] = o;
}

// ---------------- kernel 5: tf32 tensor-core GEMM + classifier --------
// h = relu([agg, xn] @ [W_l; W_r] + b_l)  (agg pre-normalized by gather)
// out = relu(h @ W1 + b1) @ W2 + b2, straight from mma fragments.
#define U_STRIDE 36
#define W_STRIDE 132
__global__ void __launch_bounds__(256)
k_fused_tc(const float4* __restrict__ x4,
           const float* __restrict__ Wl, const float* __restrict__ bl,
           const float* __restrict__ Wr, const float* __restrict__ W1,
           const float* __restrict__ b1, const float* __restrict__ W2,
           const float* __restrict__ b2, float* __restrict__ out, int N) {
    __shared__ float s_u [128 * U_STRIDE];   // U chunk  [128 rows][32 k], tf32
    __shared__ float s_w [32 * W_STRIDE];    // W chunk  [32 k][128 h], tf32
    __shared__ float s_w1t[16 * 128];        // W1^T [j][h]
    __shared__ float s_bl[128];
    __shared__ float s_scf[64], s_sbf[64];

    int t    = threadIdx.x;
    int w    = t >> 5;
    int lane = t & 31;
    int g    = lane >> 2;     // group id 0..7
    int tq   = lane & 3;      // thread-in-quad 0..3
    int m0   = blockIdx.x * 128;

    if (t < 128) s_bl[t] = bl[t];
    if (t < 64)  s_scf[t] = reinterpret_cast<const float*>(g_sc4)[t];
    else if (t < 128) s_sbf[t - 64] = reinterpret_cast<const float*>(g_sb4)[t - 64];
    for (int i = t; i < 16 * 128; i += 256) {      // W1 [128][16] -> W1T[j][h]
        int c = i & 127, j = i >> 7;
        s_w1t[j * 128 + c] = W1[c * 16 + j];
    }

    float acc[16][4];
    #pragma unroll
    for (int n = 0; n < 16; n++)
        #pragma unroll
        for (int j = 0; j < 4; j++) acc[n][j] = 0.f;

    #pragma unroll
    for (int kb = 0; kb < 4; kb++) {
        __syncthreads();
        // ---- load U chunk: 128 rows x 32 k (tf32) ----
        #pragma unroll
        for (int ii = 0; ii < 4; ii++) {
            int i = t + 256 * ii;            // 0..1023 float4 units
            int row = i >> 3, k4 = i & 7;
            int node = m0 + row;
            int kg = kb * 32 + k4 * 4;
            float4 v = make_float4(0.f, 0.f, 0.f, 0.f);
            if (node < N) {
                if (kg < D) {
                    v = g_agg4[(size_t)node * DV + (kg >> 2)];   // pre-normalized
                } else {
                    int kx = (kg - D) >> 2;
                    v = x4[(size_t)node * DV + kx];
                    int c = kx * 4;
                    v.x = fmaf(v.x, s_scf[c + 0], s_sbf[c + 0]);
                    v.y = fmaf(v.y, s_scf[c + 1], s_sbf[c + 1]);
                    v.z = fmaf(v.z, s_scf[c + 2], s_sbf[c + 2]);
                    v.w = fmaf(v.w, s_scf[c + 3], s_sbf[c + 3]);
                }
            }
            float* p = &s_u[row * U_STRIDE + k4 * 4];
            p[0] = f2tf32f(v.x); p[1] = f2tf32f(v.y);
            p[2] = f2tf32f(v.z); p[3] = f2tf32f(v.w);
        }
        // ---- load W chunk: 32 k x 128 h (tf32) ----
        #pragma unroll
        for (int ii = 0; ii < 4; ii++) {
            int i = t + 256 * ii;            // 0..1023 float4 units
            int k = i >> 5, h4 = i & 31;
            int kg = kb * 32 + k;
            const float* src = (kg < D) ? (Wl + (size_t)kg * H + h4 * 4)
                                        : (Wr + (size_t)(kg - D) * H + h4 * 4);
            float4 v = *reinterpret_cast<const float4*>(src);
            float* p = &s_w[k * W_STRIDE + h4 * 4];
            p[0] = f2tf32f(v.x); p[1] = f2tf32f(v.y);
            p[2] = f2tf32f(v.z); p[3] = f2tf32f(v.w);
        }
        __syncthreads();

        // ---- A fragments for this chunk (4 k-steps of 8) ----
        uint32_t A[4][4];
        int arow = (w * 16 + g) * U_STRIDE;
        #pragma unroll
        for (int kk = 0; kk < 4; kk++) {
            int kof = kk * 8 + tq;
            A[kk][0] = __float_as_uint(s_u[arow + kof]);
            A[kk][1] = __float_as_uint(s_u[arow + 8 * U_STRIDE + kof]);
            A[kk][2] = __float_as_uint(s_u[arow + kof + 4]);
            A[kk][3] = __float_as_uint(s_u[arow + 8 * U_STRIDE + kof + 4]);
        }
        // ---- 16 n-tiles x 4 k-steps of mma ----
        #pragma unroll
        for (int nt = 0; nt < 16; nt++) {
            int bcol = nt * 8 + g;
            #pragma unroll
            for (int kk = 0; kk < 4; kk++) {
                uint32_t b0  = __float_as_uint(s_w[(kk * 8 + tq) * W_STRIDE + bcol]);
                uint32_t b1r = __float_as_uint(s_w[(kk * 8 + tq + 4) * W_STRIDE + bcol]);
                mma_tf32(acc[nt], A[kk], b0, b1r);
            }
        }
    }

    // ---- epilogue: bias + relu + classifier, straight from fragments ----
    float part[2][16];
    #pragma unroll
    for (int rr = 0; rr < 2; rr++)
        #pragma unroll
        for (int j = 0; j < 16; j++) part[rr][j] = 0.f;

    #pragma unroll
    for (int nt = 0; nt < 16; nt++) {
        int c0 = nt * 8 + 2 * tq;
        float h00 = fmaxf(acc[nt][0] + s_bl[c0],     0.f);
        float h01 = fmaxf(acc[nt][1] + s_bl[c0 + 1], 0.f);
        float h10 = fmaxf(acc[nt][2] + s_bl[c0],     0.f);
        float h11 = fmaxf(acc[nt][3] + s_bl[c0 + 1], 0.f);
        #pragma unroll
        for (int j = 0; j < 16; j++) {
            float w0 = s_w1t[j * 128 + c0];
            float w1 = s_w1t[j * 128 + c0 + 1];
            part[0][j] += h00 * w0 + h01 * w1;
            part[1][j] += h10 * w0 + h11 * w1;
        }
    }
    #pragma unroll
    for (int rr = 0; rr < 2; rr++)
        #pragma unroll
        for (int j = 0; j < 16; j++) {
            part[rr][j] += __shfl_xor_sync(0xffffffffu, part[rr][j], 1);
            part[rr][j] += __shfl_xor_sync(0xffffffffu, part[rr][j], 2);
        }

    if (tq == 0) {
        #pragma unroll
        for (int rr = 0; rr < 2; rr++) {
            int node = m0 + w * 16 + g + rr * 8;
            if (node < N) {
                float o0 = b2[0], o1 = b2[1];
                #pragma unroll
                for (int j = 0; j < 16; j++) {
                    float tv = fmaxf(part[rr][j] + b1[j], 0.f);
                    o0 += tv * W2[j * 2 + 0];
                    o1 += tv * W2[j * 2 + 1];
                }
                out[(size_t)node * 2 + 0] = o0;
                out[(size_t)node * 2 + 1] = o1;
            }
        }
    }
}

// ---------------- launcher --------------------------------------------
extern "C" void kernel_launch(void* const* d_in, const int* in_sizes, int n_in,
                              void* d_out, int out_size) {
    const float4* x4 = (const float4*)d_in[0];
    const float2* x2 = (const float2*)d_in[0];
    const int*    ei = (const int*)d_in[1];   // int64 ref -> int32 in harness
    int N = in_sizes[0] / D;
    int E = in_sizes[1] / 2;

    const int want[9] = {64, 64, 8192, 128, 8192, 2048, 16, 32, 2};
    const float* wptr[9] = {nullptr, nullptr, nullptr, nullptr, nullptr,
                            nullptr, nullptr, nullptr, nullptr};
    int j = 0;
    for (int i = 2; i < n_in && j < 9; i++) {
        if (in_sizes[i] == want[j]) { wptr[j] = (const float*)d_in[i]; j++; }
    }
    const float *gamma = wptr[0], *beta = wptr[1], *Wl = wptr[2], *bl = wptr[3],
                *Wr = wptr[4], *W1 = wptr[5], *b1 = wptr[6], *W2 = wptr[7],
                *b2 = wptr[8];
    float* out = (float*)d_out;

    k_stats<<<592, 256>>>(x4, ei, gamma, beta, N, E);
    k_offsets<<<(N + 1023) / 1024, 1024>>>(N);
    k_fill<<<4096, 256>>>(ei, E, N);
    k_gather<<<(N + 7) / 8, 256>>>(x2, N);
    k_fused_tc<<<(N + 127) / 128, 256>>>(x4, Wl, bl, Wr, W1, b1, W2, b2, out, N);
}